// round 2
// baseline (speedup 1.0000x reference)
#include <cuda_runtime.h>
#include <cstdint>

#define TPB 256

#define NBATCH 2048
#define CDIM 192
#define NPOS 64
#define NHEAD 6
#define NGRP 3
#define NS 16

#define RSX 66     // row stride for x / attn-out tile [192][64] (2-way-conflict stores, b64-aligned loads)
#define RSQ 68     // row stride for q tile
#define RSW 388    // row stride (floats) for duplicated weight chunk [64][192*2]
#define RS2 16     // row stride for samp/k/v tiles [192][16]

// shared-memory layout (float offsets)
#define O_XS    0                    // 192*66 = 12672 (x; later kv plain weights; later attn-out)
#define O_QS    12672                // 192*68 = 13056
#define O_R3    25728                // 64*388 = 24832 (dup weight chunk)  OR  samp/k/v
#define O_SAMP  (O_R3)               // 192*16 = 3072
#define O_KS    (O_R3 + 3072)
#define O_VS    (O_R3 + 6144)
#define O_RPE   50560                // 1350
#define O_DWW   51910                // 576
#define O_DWB   52486
#define O_LNG   52550
#define O_LNB   52614
#define O_PWW   52678                // 128
#define O_POS   52806                // 96
#define O_SMPW  52902                // 192
#define O_SMPI  53094                // 192 ints
#define SMEMF   53286
#define SMEM_BYTES (SMEMF * 4)

#define Y_SIZE   (NBATCH * CDIM * NPOS)
#define PR_SIZE  (NBATCH * NGRP * NS * 2)
#define POS_OFF  Y_SIZE
#define REF_OFF  (Y_SIZE + PR_SIZE)

typedef unsigned long long ull;

__device__ __forceinline__ ull ffma2(ull a, ull b, ull c) {
    ull d;
    asm volatile("fma.rn.f32x2 %0, %1, %2, %3;" : "=l"(d) : "l"(a), "l"(b), "l"(c));
    return d;
}
__device__ __forceinline__ ull pk2(float lo, float hi) {
    ull r;
    asm volatile("mov.b64 %0, {%1, %2};" : "=l"(r) : "f"(lo), "f"(hi));
    return r;
}
__device__ __forceinline__ void unpk2(float& lo, float& hi, ull v) {
    asm volatile("mov.b64 {%0, %1}, %2;" : "=f"(lo), "=f"(hi) : "l"(v));
}

// one 2-k-step of the f32x2 GEMM inner loop; literal byte offsets so ptxas
// folds them into the LDS immediate field.
#define QSTEP(WO, XA0, XB0, XA1, XB1) do {                                              \
    ull w0A,w0B,w1A,w1B,w2A,w2B,w3A,w3B,xs0,xt0,xs1,xt1;                                \
    asm volatile("ld.shared.v2.b64 {%0,%1}, [%2+" #WO "];":"=l"(w0A),"=l"(w0B):"r"(wa0));\
    asm volatile("ld.shared.v2.b64 {%0,%1}, [%2+" #WO "];":"=l"(w1A),"=l"(w1B):"r"(wa1));\
    asm volatile("ld.shared.v2.b64 {%0,%1}, [%2+" #WO "];":"=l"(w2A),"=l"(w2B):"r"(wa2));\
    asm volatile("ld.shared.v2.b64 {%0,%1}, [%2+" #WO "];":"=l"(w3A),"=l"(w3B):"r"(wa3));\
    asm volatile("ld.shared.b64 %0, [%1+" #XA0 "];":"=l"(xs0):"r"(xab));                \
    asm volatile("ld.shared.b64 %0, [%1+" #XB0 "];":"=l"(xt0):"r"(xab));                \
    asm volatile("ld.shared.b64 %0, [%1+" #XA1 "];":"=l"(xs1):"r"(xab));                \
    asm volatile("ld.shared.b64 %0, [%1+" #XB1 "];":"=l"(xt1):"r"(xab));                \
    acc00 = ffma2(w0A, xs0, acc00); acc01 = ffma2(w0A, xt0, acc01);                     \
    acc10 = ffma2(w1A, xs0, acc10); acc11 = ffma2(w1A, xt0, acc11);                     \
    acc20 = ffma2(w2A, xs0, acc20); acc21 = ffma2(w2A, xt0, acc21);                     \
    acc30 = ffma2(w3A, xs0, acc30); acc31 = ffma2(w3A, xt0, acc31);                     \
    acc00 = ffma2(w0B, xs1, acc00); acc01 = ffma2(w0B, xt1, acc01);                     \
    acc10 = ffma2(w1B, xs1, acc10); acc11 = ffma2(w1B, xt1, acc11);                     \
    acc20 = ffma2(w2B, xs1, acc20); acc21 = ffma2(w2B, xt1, acc21);                     \
    acc30 = ffma2(w3B, xs1, acc30); acc31 = ffma2(w3B, xt1, acc31);                     \
} while (0)

// stage 64 output rows of W, each value duplicated into a float2 pair
__device__ __forceinline__ void stage_w_dup(const float* __restrict__ W, int co0,
                                            float* __restrict__ sm, int tid)
{
    for (int t = tid; t < 64 * 192; t += TPB) {
        int i = t / 192;
        int c = t - i * 192;
        float w = W[(co0 + i) * 192 + c];
        *(float2*)&sm[O_R3 + i * RSW + c * 2] = make_float2(w, w);
    }
}

// 192x64 GEMM, K=192, f32x2 packed: out[co][p] = bias[co] + sum_c W[co][c]*in[c][p]
template <bool TO_SMEM>
__device__ __forceinline__ void gemm_big(const float* __restrict__ W, const float* __restrict__ bias,
                                         float* __restrict__ gout,
                                         float* __restrict__ sm, uint32_t sb, int tid)
{
    const int cob = tid >> 4;        // 16 co blocks of 4
    const int pq = (tid & 15) * 4;   // 4 positions
    for (int chunk = 0; chunk < 3; ++chunk) {
        const int co0 = chunk * 64;
        stage_w_dup(W, co0, sm, tid);
        __syncthreads();
        const int co = cob * 4;
        ull acc00, acc01, acc10, acc11, acc20, acc21, acc30, acc31;
        {
            float b0 = bias[co0 + co + 0], b1 = bias[co0 + co + 1];
            float b2 = bias[co0 + co + 2], b3 = bias[co0 + co + 3];
            acc00 = pk2(b0, b0); acc01 = pk2(b0, b0);
            acc10 = pk2(b1, b1); acc11 = pk2(b1, b1);
            acc20 = pk2(b2, b2); acc21 = pk2(b2, b2);
            acc30 = pk2(b3, b3); acc31 = pk2(b3, b3);
        }
        uint32_t xbase = sb + (uint32_t)(O_XS + pq) * 4u;
        uint32_t wb0 = sb + (uint32_t)(O_R3 + (co + 0) * RSW) * 4u;
        uint32_t wb1 = wb0 + RSW * 4u;
        uint32_t wb2 = wb1 + RSW * 4u;
        uint32_t wb3 = wb2 + RSW * 4u;
#pragma unroll 1
        for (int cb = 0; cb < 192; cb += 16) {
            uint32_t xab = xbase + (uint32_t)cb * (RSX * 4u);
            uint32_t wa0 = wb0 + (uint32_t)cb * 8u;
            uint32_t wa1 = wb1 + (uint32_t)cb * 8u;
            uint32_t wa2 = wb2 + (uint32_t)cb * 8u;
            uint32_t wa3 = wb3 + (uint32_t)cb * 8u;
            QSTEP(0,    0,    8,    264,  272);
            QSTEP(16,   528,  536,  792,  800);
            QSTEP(32,   1056, 1064, 1320, 1328);
            QSTEP(48,   1584, 1592, 1848, 1856);
            QSTEP(64,   2112, 2120, 2376, 2384);
            QSTEP(80,   2640, 2648, 2904, 2912);
            QSTEP(96,   3168, 3176, 3432, 3440);
            QSTEP(112,  3696, 3704, 3960, 3968);
        }
#pragma unroll
        for (int i = 0; i < 4; ++i) {
            ull aA = (i == 0) ? acc00 : (i == 1) ? acc10 : (i == 2) ? acc20 : acc30;
            ull aB = (i == 0) ? acc01 : (i == 1) ? acc11 : (i == 2) ? acc21 : acc31;
            float4 v;
            unpk2(v.x, v.y, aA);
            unpk2(v.z, v.w, aB);
            if (TO_SMEM) {
                *(float4*)&sm[O_QS + (co0 + co + i) * RSQ + pq] = v;
            } else {
                *(float4*)&gout[(co0 + co + i) * 64 + pq] = v;
            }
        }
        __syncthreads();
    }
}

// 192x16 GEMM, K=192 (scalar; small). plain weights staged into XS region (x is dead).
__device__ __forceinline__ void gemm_small(const float* __restrict__ W, const float* __restrict__ bias,
                                           int outOff, float* __restrict__ sm, int tid)
{
    const int cob = tid >> 4;
    const int s = tid & 15;
    for (int chunk = 0; chunk < 3; ++chunk) {
        const int co0 = chunk * 64;
        for (int t = tid; t < 64 * 192; t += TPB) {
            int i = t / 192;
            int c = t - i * 192;
            sm[O_XS + i * 192 + c] = W[(co0 + i) * 192 + c];
        }
        __syncthreads();
        const int co = cob * 4;
        float acc[4];
#pragma unroll
        for (int i = 0; i < 4; ++i) acc[i] = bias[co0 + co + i];
        const float* w0 = &sm[O_XS + (co + 0) * 192];
        const float* w1 = &sm[O_XS + (co + 1) * 192];
        const float* w2 = &sm[O_XS + (co + 2) * 192];
        const float* w3 = &sm[O_XS + (co + 3) * 192];
#pragma unroll 4
        for (int c = 0; c < 192; ++c) {
            float xv = sm[O_SAMP + c * RS2 + s];
            acc[0] += w0[c] * xv;
            acc[1] += w1[c] * xv;
            acc[2] += w2[c] * xv;
            acc[3] += w3[c] * xv;
        }
#pragma unroll
        for (int i = 0; i < 4; ++i) sm[outOff + (co0 + co + i) * RS2 + s] = acc[i];
        __syncthreads();
    }
}

__global__ void __launch_bounds__(TPB, 1)
dat_fused_kernel(const float* __restrict__ x,
                 const float* __restrict__ wq, const float* __restrict__ bq,
                 const float* __restrict__ wk, const float* __restrict__ bk,
                 const float* __restrict__ wv, const float* __restrict__ bv,
                 const float* __restrict__ wo, const float* __restrict__ bo,
                 const float* __restrict__ dww, const float* __restrict__ dwb,
                 const float* __restrict__ lng, const float* __restrict__ lnb,
                 const float* __restrict__ pww, const float* __restrict__ rpe,
                 float* __restrict__ out, int writePR)
{
    extern __shared__ float sm[];
    const int b = blockIdx.x;
    const int tid = threadIdx.x;
    const uint32_t sb = (uint32_t)__cvta_generic_to_shared(sm);

    // ---- stage x (transpose to [c][p], stride 66) and all small params ----
    const float* xb = x + (size_t)b * (NPOS * CDIM);
    for (int t = tid; t < NPOS * CDIM; t += TPB) {
        int p = t / CDIM;
        int c = t - p * CDIM;
        sm[O_XS + c * RSX + p] = xb[t];
    }
    for (int t = tid; t < 1350; t += TPB) sm[O_RPE + t] = rpe[t];
    for (int t = tid; t < 576; t += TPB) sm[O_DWW + t] = dww[t];
    if (tid < 64) {
        sm[O_DWB + tid] = dwb[tid];
        sm[O_LNG + tid] = lng[tid];
        sm[O_LNB + tid] = lnb[tid];
    }
    if (tid >= 64 && tid < 192) sm[O_PWW + tid - 64] = pww[tid - 64];
    __syncthreads();

    // ---- q = Wq x + bq ----
    gemm_big<true>(wq, bq, nullptr, sm, sb, tid);

    // ---- offset network: 48 items (group g, sample s) ----
    const int warp = tid >> 5, lane = tid & 31;
    for (int k = 0; k < 6; ++k) {
        const int item = warp * 6 + k;
        const int g = item >> 4;
        const int s = item & 15;
        const int si = s >> 2, sj = s & 3;
        const int ch0 = lane, ch1 = lane + 32;
        float v0 = sm[O_DWB + ch0];
        float v1 = sm[O_DWB + ch1];
        const int iy0 = 2 * si - 1, ix0 = 2 * sj - 1;
#pragma unroll
        for (int di = 0; di < 3; ++di) {
            int iy = iy0 + di;
            if (iy < 0 || iy > 7) continue;
#pragma unroll
            for (int dj = 0; dj < 3; ++dj) {
                int ix = ix0 + dj;
                if (ix < 0 || ix > 7) continue;
                float q0 = sm[O_QS + (g * 64 + ch0) * RSQ + iy * 8 + ix];
                float q1 = sm[O_QS + (g * 64 + ch1) * RSQ + iy * 8 + ix];
                v0 += sm[O_DWW + ch0 * 9 + di * 3 + dj] * q0;
                v1 += sm[O_DWW + ch1 * 9 + di * 3 + dj] * q1;
            }
        }
        float ssum = v0 + v1, ssq = v0 * v0 + v1 * v1;
#pragma unroll
        for (int o = 16; o > 0; o >>= 1) {
            ssum += __shfl_xor_sync(0xffffffffu, ssum, o);
            ssq += __shfl_xor_sync(0xffffffffu, ssq, o);
        }
        float mu = ssum * (1.0f / 64.0f);
        float var = ssq * (1.0f / 64.0f) - mu * mu;
        float rstd = rsqrtf(var + 1e-5f);
        v0 = (v0 - mu) * rstd * sm[O_LNG + ch0] + sm[O_LNB + ch0];
        v1 = (v1 - mu) * rstd * sm[O_LNG + ch1] + sm[O_LNB + ch1];
        v0 = 0.5f * v0 * (1.0f + erff(v0 * 0.70710678118654752f));
        v1 = 0.5f * v1 * (1.0f + erff(v1 * 0.70710678118654752f));
        float o0 = sm[O_PWW + ch0] * v0 + sm[O_PWW + ch1] * v1;
        float o1 = sm[O_PWW + 64 + ch0] * v0 + sm[O_PWW + 64 + ch1] * v1;
#pragma unroll
        for (int o = 16; o > 0; o >>= 1) {
            o0 += __shfl_xor_sync(0xffffffffu, o0, o);
            o1 += __shfl_xor_sync(0xffffffffu, o1, o);
        }
        if (lane == 0) {
            float offy = tanhf(o0) * (2.0f / 3.0f);
            float offx = tanhf(o1) * (2.0f / 3.0f);
            float ry = (2 * si - 3) * 0.25f;
            float rx = (2 * sj - 3) * 0.25f;
            float py = offy + ry;
            float px = offx + rx;
            sm[O_POS + item * 2 + 0] = py;
            sm[O_POS + item * 2 + 1] = px;
            float gx = (px + 1.0f) * 3.5f;
            float gy = (py + 1.0f) * 3.5f;
            float x0f = floorf(gx), y0f = floorf(gy);
            int jx0 = (int)x0f, jy0 = (int)y0f;
            float wx1 = gx - x0f, wy1 = gy - y0f;
            float wxs[2] = {1.0f - wx1, wx1};
            float wys[2] = {1.0f - wy1, wy1};
            int* smpI = (int*)sm;
#pragma unroll
            for (int n = 0; n < 4; ++n) {
                int xi = jx0 + (n & 1);
                int yi = jy0 + (n >> 1);
                bool val = (xi >= 0 && xi <= 7 && yi >= 0 && yi <= 7);
                sm[O_SMPW + item * 4 + n] = val ? wxs[n & 1] * wys[n >> 1] : 0.0f;
                smpI[O_SMPI + item * 4 + n] = val ? (yi * 8 + xi) : 0;
            }
            if (writePR) {
                size_t po = ((size_t)b * 48 + item) * 2;
                out[POS_OFF + po + 0] = py;
                out[POS_OFF + po + 1] = px;
                out[REF_OFF + po + 0] = ry;
                out[REF_OFF + po + 1] = rx;
            }
        }
    }
    __syncthreads();

    // ---- bilinear sample x at pos -> samp[c][s] ----
    for (int t = tid; t < CDIM * NS; t += TPB) {
        int c = t >> 4;
        int s = t & 15;
        int item = (c >> 6) * 16 + s;
        const float* wp = &sm[O_SMPW + item * 4];
        const int* ip = ((const int*)sm) + O_SMPI + item * 4;
        const float* row = &sm[O_XS + c * RSX];
        sm[O_SAMP + c * RS2 + s] =
            wp[0] * row[ip[0]] + wp[1] * row[ip[1]] + wp[2] * row[ip[2]] + wp[3] * row[ip[3]];
    }
    __syncthreads();

    // ---- k, v projections on sampled features ----
    gemm_small(wk, bk, O_KS, sm, tid);
    gemm_small(wv, bv, O_VS, sm, tid);

    // ---- attention ----
    for (int it = tid; it < NHEAD * NPOS; it += TPB) {
        const int h = it >> 6;
        const int p = it & 63;
        const int g = h >> 1;
        float a[16];
#pragma unroll
        for (int s = 0; s < 16; ++s) a[s] = 0.0f;
#pragma unroll 4
        for (int c = 0; c < 32; ++c) {
            float qv = sm[O_QS + (h * 32 + c) * RSQ + p];
            const float4* kr = (const float4*)&sm[O_KS + (h * 32 + c) * RS2];
            float4 k0 = kr[0], k1 = kr[1], k2 = kr[2], k3 = kr[3];
            a[0] += qv * k0.x; a[1] += qv * k0.y; a[2] += qv * k0.z; a[3] += qv * k0.w;
            a[4] += qv * k1.x; a[5] += qv * k1.y; a[6] += qv * k1.z; a[7] += qv * k1.w;
            a[8] += qv * k2.x; a[9] += qv * k2.y; a[10] += qv * k2.z; a[11] += qv * k2.w;
            a[12] += qv * k3.x; a[13] += qv * k3.y; a[14] += qv * k3.z; a[15] += qv * k3.w;
        }
        const float scale = 0.17677669529663687f;
        float qy = (2 * (p >> 3) - 7) * 0.125f;
        float qx = (2 * (p & 7) - 7) * 0.125f;
        const float* rpeh = &sm[O_RPE + h * 225];
        float mx = -1e30f;
#pragma unroll
        for (int s = 0; s < 16; ++s) {
            float py = sm[O_POS + (g * 16 + s) * 2 + 0];
            float px = sm[O_POS + (g * 16 + s) * 2 + 1];
            float dy = (qy - py) * 0.5f;
            float dx = (qx - px) * 0.5f;
            float gx = (dx + 1.0f) * 7.0f;
            float gy = (dy + 1.0f) * 7.0f;
            float x0f = floorf(gx), y0f = floorf(gy);
            int jx0 = (int)x0f, jy0 = (int)y0f;
            float wx1 = gx - x0f, wy1 = gy - y0f;
            float bias = 0.0f;
            if (jx0 >= 0 && jx0 <= 14 && jy0 >= 0 && jy0 <= 14)
                bias += (1.0f - wx1) * (1.0f - wy1) * rpeh[jy0 * 15 + jx0];
            if (jx0 + 1 >= 0 && jx0 + 1 <= 14 && jy0 >= 0 && jy0 <= 14)
                bias += wx1 * (1.0f - wy1) * rpeh[jy0 * 15 + jx0 + 1];
            if (jx0 >= 0 && jx0 <= 14 && jy0 + 1 >= 0 && jy0 + 1 <= 14)
                bias += (1.0f - wx1) * wy1 * rpeh[(jy0 + 1) * 15 + jx0];
            if (jx0 + 1 >= 0 && jx0 + 1 <= 14 && jy0 + 1 >= 0 && jy0 + 1 <= 14)
                bias += wx1 * wy1 * rpeh[(jy0 + 1) * 15 + jx0 + 1];
            a[s] = a[s] * scale + bias;
            mx = fmaxf(mx, a[s]);
        }
        float ssum = 0.0f;
#pragma unroll
        for (int s = 0; s < 16; ++s) { a[s] = __expf(a[s] - mx); ssum += a[s]; }
        float inv = 1.0f / ssum;
#pragma unroll
        for (int s = 0; s < 16; ++s) a[s] *= inv;
        for (int cl = 0; cl < 32; ++cl) {
            int c = h * 32 + cl;
            const float4* vr = (const float4*)&sm[O_VS + c * RS2];
            float4 v0 = vr[0], v1 = vr[1], v2 = vr[2], v3 = vr[3];
            float acc = a[0]*v0.x + a[1]*v0.y + a[2]*v0.z + a[3]*v0.w
                      + a[4]*v1.x + a[5]*v1.y + a[6]*v1.z + a[7]*v1.w
                      + a[8]*v2.x + a[9]*v2.y + a[10]*v2.z + a[11]*v2.w
                      + a[12]*v3.x + a[13]*v3.y + a[14]*v3.z + a[15]*v3.w;
            sm[O_XS + c * RSX + p] = acc;
        }
    }
    __syncthreads();

    // ---- y = Wo out + bo (direct to gmem) ----
    gemm_big<false>(wo, bo, out + (size_t)b * (CDIM * NPOS), sm, sb, tid);
}

extern "C" void kernel_launch(void* const* d_in, const int* in_sizes, int n_in,
                              void* d_out, int out_size)
{
    (void)in_sizes; (void)n_in;
    const float* x   = (const float*)d_in[0];
    const float* wq  = (const float*)d_in[1];
    const float* bq  = (const float*)d_in[2];
    const float* wk  = (const float*)d_in[3];
    const float* bk  = (const float*)d_in[4];
    const float* wv  = (const float*)d_in[5];
    const float* bv  = (const float*)d_in[6];
    const float* wo  = (const float*)d_in[7];
    const float* bo  = (const float*)d_in[8];
    const float* dww = (const float*)d_in[9];
    const float* dwb = (const float*)d_in[10];
    const float* lng = (const float*)d_in[11];
    const float* lnb = (const float*)d_in[12];
    const float* pww = (const float*)d_in[13];
    const float* rpe = (const float*)d_in[14];
    float* out = (float*)d_out;

    int writePR = (out_size >= (REF_OFF + PR_SIZE)) ? 1 : 0;

    cudaFuncSetAttribute(dat_fused_kernel,
                         cudaFuncAttributeMaxDynamicSharedMemorySize, SMEM_BYTES);
    dat_fused_kernel<<<NBATCH, TPB, SMEM_BYTES>>>(
        x, wq, bq, wk, bk, wv, bv, wo, bo, dww, dwb, lng, lnb, pww, rpe, out, writePR);
}

// round 5
// speedup vs baseline: 1.2530x; 1.2530x over previous
#include <cuda_runtime.h>
#include <cstdint>

#define TPB 512

#define NBATCH 2048
#define CDIM 192
#define NPOS 64
#define NHEAD 6
#define NGRP 3
#define NS 16

#define RSX 68     // row stride for x / attn-out tile [192][64]
#define RSQ 68     // row stride for q tile [192][64]
#define RST 64     // row stride for transposed weight chunk [192 k][64 co]
#define RSS 16     // row stride for samp/k/v tiles [192][16]

// shared-memory layout (float offsets)
#define O_XS    0          // 192*68 = 13056 (x; later attn-out)
#define O_QS    13056      // 13056
#define O_WT    26112      // 192*64 = 12288 transposed weight chunk
#define O_SAMP  38400      // 192*16 = 3072
#define O_KS    41472      // 3072
#define O_VS    44544      // 3072
#define O_RPE   47616      // 1350
#define O_DWW   48966      // 576
#define O_DWB   49542      // 64
#define O_LNG   49606      // 64
#define O_LNB   49670      // 64
#define O_PWW   49734      // 128
#define O_POS   49862      // 96
#define O_SMPW  49958      // 192
#define O_SMPI  50150      // 192 (ints)
#define SMEMF   50342
#define SMEM_BYTES (SMEMF * 4)

#define Y_SIZE   (NBATCH * CDIM * NPOS)
#define PR_SIZE  (NBATCH * NGRP * NS * 2)
#define POS_OFF  Y_SIZE
#define REF_OFF  (Y_SIZE + PR_SIZE)

// ---- weight chunk staging: 64 rows x 192 cols, stored transposed wT[k][co] ----
// Each thread owns row i = tid&63, col-quads cq = (tid>>6) + j*8 (j=0..5): 24 floats.
__device__ __forceinline__ void ldg_chunk(const float* __restrict__ W, int co0,
                                          int tid, float4 r[6])
{
    const int i = tid & 63;
    const int cq = tid >> 6;    // 0..7
#pragma unroll
    for (int j = 0; j < 6; ++j)
        r[j] = __ldg((const float4*)&W[(co0 + i) * 192 + (cq + j * 8) * 4]);
}

__device__ __forceinline__ void sts_chunk(float* __restrict__ sm, int tid, const float4 r[6])
{
    const int i = tid & 63;
    const int cq = tid >> 6;
#pragma unroll
    for (int j = 0; j < 6; ++j) {
        const int c = (cq + j * 8) * 4;
        sm[O_WT + (c + 0) * RST + i] = r[j].x;
        sm[O_WT + (c + 1) * RST + i] = r[j].y;
        sm[O_WT + (c + 2) * RST + i] = r[j].z;
        sm[O_WT + (c + 3) * RST + i] = r[j].w;
    }
}

// 192x64 GEMM, K=192: out[co][p] = bias[co] + sum_k W[co][k] * in[k][p]
// Thread tile: 2 co x 4 p. wreg holds chunk 0 on entry (prefetched by caller).
template <bool TO_SMEM>
__device__ __forceinline__ void gemm_big(const float* __restrict__ W, const float* __restrict__ bias,
                                         int inOff, float* __restrict__ gout,
                                         float* __restrict__ sm, int tid, float4 wreg[6])
{
    const int col = (tid >> 4) * 2;    // 0..62 (local co within chunk)
    const int p = (tid & 15) * 4;
    for (int chunk = 0; chunk < 3; ++chunk) {
        const int co0 = chunk * 64;
        if (chunk) __syncthreads();            // protect WT from previous chunk's readers
        sts_chunk(sm, tid, wreg);
        __syncthreads();
        if (chunk < 2) ldg_chunk(W, co0 + 64, tid, wreg);   // overlap with compute below
        const float b0 = bias[co0 + col];
        const float b1 = bias[co0 + col + 1];
        float4 a0 = make_float4(b0, b0, b0, b0);
        float4 a1 = make_float4(b1, b1, b1, b1);
#pragma unroll 4
        for (int k = 0; k < 192; ++k) {
            float2 w = *(const float2*)&sm[O_WT + k * RST + col];
            float4 xv = *(const float4*)&sm[inOff + k * RSX + p];
            a0.x += w.x * xv.x; a0.y += w.x * xv.y; a0.z += w.x * xv.z; a0.w += w.x * xv.w;
            a1.x += w.y * xv.x; a1.y += w.y * xv.y; a1.z += w.y * xv.z; a1.w += w.y * xv.w;
        }
        if (TO_SMEM) {
            *(float4*)&sm[O_QS + (co0 + col) * RSQ + p] = a0;
            *(float4*)&sm[O_QS + (co0 + col + 1) * RSQ + p] = a1;
        } else {
            *(float4*)&gout[(co0 + col) * 64 + p] = a0;
            *(float4*)&gout[(co0 + col + 1) * 64 + p] = a1;
        }
    }
    __syncthreads();
}

__global__ void __launch_bounds__(TPB, 1)
dat_fused_kernel(const float* __restrict__ x,
                 const float* __restrict__ wq, const float* __restrict__ bq,
                 const float* __restrict__ wk, const float* __restrict__ bk,
                 const float* __restrict__ wv, const float* __restrict__ bv,
                 const float* __restrict__ wo, const float* __restrict__ bo,
                 const float* __restrict__ dww, const float* __restrict__ dwb,
                 const float* __restrict__ lng, const float* __restrict__ lnb,
                 const float* __restrict__ pww, const float* __restrict__ rpe,
                 float* __restrict__ out, int writePR)
{
    extern __shared__ float sm[];
    const int b = blockIdx.x;
    const int tid = threadIdx.x;

    // prefetch q-proj weight chunk 0 while staging x
    float4 wreg[6];
    ldg_chunk(wq, 0, tid, wreg);

    // ---- stage x (transpose to [c][p]) and small params ----
    const float* xb = x + (size_t)b * (NPOS * CDIM);
    for (int t = tid; t < NPOS * CDIM; t += TPB) {
        int p = t / CDIM;
        int c = t - p * CDIM;
        sm[O_XS + c * RSX + p] = xb[t];
    }
    for (int t = tid; t < 1350; t += TPB) sm[O_RPE + t] = rpe[t];
    for (int t = tid; t < 576; t += TPB) sm[O_DWW + t] = dww[t];
    if (tid < 64) {
        sm[O_DWB + tid] = dwb[tid];
        sm[O_LNG + tid] = lng[tid];
        sm[O_LNB + tid] = lnb[tid];
    }
    if (tid >= 64 && tid < 192) sm[O_PWW + tid - 64] = pww[tid - 64];
    __syncthreads();

    // ---- q = Wq x + bq ----
    gemm_big<true>(wq, bq, O_XS, nullptr, sm, tid, wreg);

    // ---- offset network: 48 items (group g, sample s), 3 per warp ----
    const int warp = tid >> 5, lane = tid & 31;
    for (int kk = 0; kk < 3; ++kk) {
        const int item = warp * 3 + kk;
        const int g = item >> 4;
        const int s = item & 15;
        const int si = s >> 2, sj = s & 3;
        const int ch0 = lane, ch1 = lane + 32;
        float v0 = sm[O_DWB + ch0];
        float v1 = sm[O_DWB + ch1];
        const int iy0 = 2 * si - 1, ix0 = 2 * sj - 1;
#pragma unroll
        for (int di = 0; di < 3; ++di) {
            int iy = iy0 + di;
            if (iy < 0 || iy > 7) continue;
#pragma unroll
            for (int dj = 0; dj < 3; ++dj) {
                int ix = ix0 + dj;
                if (ix < 0 || ix > 7) continue;
                float q0 = sm[O_QS + (g * 64 + ch0) * RSQ + iy * 8 + ix];
                float q1 = sm[O_QS + (g * 64 + ch1) * RSQ + iy * 8 + ix];
                v0 += sm[O_DWW + ch0 * 9 + di * 3 + dj] * q0;
                v1 += sm[O_DWW + ch1 * 9 + di * 3 + dj] * q1;
            }
        }
        float ssum = v0 + v1, ssq = v0 * v0 + v1 * v1;
#pragma unroll
        for (int o = 16; o > 0; o >>= 1) {
            ssum += __shfl_xor_sync(0xffffffffu, ssum, o);
            ssq += __shfl_xor_sync(0xffffffffu, ssq, o);
        }
        float mu = ssum * (1.0f / 64.0f);
        float var = ssq * (1.0f / 64.0f) - mu * mu;
        float rstd = rsqrtf(var + 1e-5f);
        v0 = (v0 - mu) * rstd * sm[O_LNG + ch0] + sm[O_LNB + ch0];
        v1 = (v1 - mu) * rstd * sm[O_LNG + ch1] + sm[O_LNB + ch1];
        v0 = 0.5f * v0 * (1.0f + erff(v0 * 0.70710678118654752f));
        v1 = 0.5f * v1 * (1.0f + erff(v1 * 0.70710678118654752f));
        float o0 = sm[O_PWW + ch0] * v0 + sm[O_PWW + ch1] * v1;
        float o1 = sm[O_PWW + 64 + ch0] * v0 + sm[O_PWW + 64 + ch1] * v1;
#pragma unroll
        for (int o = 16; o > 0; o >>= 1) {
            o0 += __shfl_xor_sync(0xffffffffu, o0, o);
            o1 += __shfl_xor_sync(0xffffffffu, o1, o);
        }
        if (lane == 0) {
            float offy = tanhf(o0) * (2.0f / 3.0f);
            float offx = tanhf(o1) * (2.0f / 3.0f);
            float ry = (2 * si - 3) * 0.25f;
            float rx = (2 * sj - 3) * 0.25f;
            float py = offy + ry;
            float px = offx + rx;
            sm[O_POS + item * 2 + 0] = py;
            sm[O_POS + item * 2 + 1] = px;
            float gx = (px + 1.0f) * 3.5f;
            float gy = (py + 1.0f) * 3.5f;
            float x0f = floorf(gx), y0f = floorf(gy);
            int jx0 = (int)x0f, jy0 = (int)y0f;
            float wx1 = gx - x0f, wy1 = gy - y0f;
            float wxs[2] = {1.0f - wx1, wx1};
            float wys[2] = {1.0f - wy1, wy1};
            int* smpI = (int*)sm;
#pragma unroll
            for (int n = 0; n < 4; ++n) {
                int xi = jx0 + (n & 1);
                int yi = jy0 + (n >> 1);
                bool val = (xi >= 0 && xi <= 7 && yi >= 0 && yi <= 7);
                sm[O_SMPW + item * 4 + n] = val ? wxs[n & 1] * wys[n >> 1] : 0.0f;
                smpI[O_SMPI + item * 4 + n] = val ? (yi * 8 + xi) : 0;
            }
            if (writePR) {
                size_t po = ((size_t)b * 48 + item) * 2;
                out[POS_OFF + po + 0] = py;
                out[POS_OFF + po + 1] = px;
                out[REF_OFF + po + 0] = ry;
                out[REF_OFF + po + 1] = rx;
            }
        }
    }
    __syncthreads();

    // ---- bilinear sample x at pos -> samp[c][s] ----
    for (int t = tid; t < CDIM * NS; t += TPB) {
        int c = t >> 4;
        int s = t & 15;
        int item = (c >> 6) * 16 + s;
        const float* wp = &sm[O_SMPW + item * 4];
        const int* ip = ((const int*)sm) + O_SMPI + item * 4;
        const float* row = &sm[O_XS + c * RSX];
        sm[O_SAMP + c * RSS + s] =
            wp[0] * row[ip[0]] + wp[1] * row[ip[1]] + wp[2] * row[ip[2]] + wp[3] * row[ip[3]];
    }
    __syncthreads();

    // ---- k, v projections: weights direct from L2, thread = (co, 8 s-cols) ----
    if (tid < 384) {
        const int co = tid >> 1;
        const int sh = (tid & 1) * 8;
        const float bkc = bk[co], bvc = bv[co];
        float4 ak0 = make_float4(bkc, bkc, bkc, bkc), ak1 = ak0;
        float4 av0 = make_float4(bvc, bvc, bvc, bvc), av1 = av0;
#pragma unroll 4
        for (int k4 = 0; k4 < 48; ++k4) {
            float4 wk4 = __ldg((const float4*)&wk[co * 192 + k4 * 4]);
            float4 wv4 = __ldg((const float4*)&wv[co * 192 + k4 * 4]);
#pragma unroll
            for (int j = 0; j < 4; ++j) {
                float wkj = (j == 0) ? wk4.x : (j == 1) ? wk4.y : (j == 2) ? wk4.z : wk4.w;
                float wvj = (j == 0) ? wv4.x : (j == 1) ? wv4.y : (j == 2) ? wv4.z : wv4.w;
                float4 s0 = *(const float4*)&sm[O_SAMP + (k4 * 4 + j) * RSS + sh];
                float4 s1 = *(const float4*)&sm[O_SAMP + (k4 * 4 + j) * RSS + sh + 4];
                ak0.x += wkj * s0.x; ak0.y += wkj * s0.y; ak0.z += wkj * s0.z; ak0.w += wkj * s0.w;
                ak1.x += wkj * s1.x; ak1.y += wkj * s1.y; ak1.z += wkj * s1.z; ak1.w += wkj * s1.w;
                av0.x += wvj * s0.x; av0.y += wvj * s0.y; av0.z += wvj * s0.z; av0.w += wvj * s0.w;
                av1.x += wvj * s1.x; av1.y += wvj * s1.y; av1.z += wvj * s1.z; av1.w += wvj * s1.w;
            }
        }
        *(float4*)&sm[O_KS + co * RSS + sh] = ak0;
        *(float4*)&sm[O_KS + co * RSS + sh + 4] = ak1;
        *(float4*)&sm[O_VS + co * RSS + sh] = av0;
        *(float4*)&sm[O_VS + co * RSS + sh + 4] = av1;
    }
    __syncthreads();

    // prefetch o-proj weight chunk 0; attention below hides the L2 latency
    ldg_chunk(wo, 0, tid, wreg);

    // ---- attention: item = (head, query position), 384 items ----
    for (int it = tid; it < NHEAD * NPOS; it += TPB) {
        const int h = it >> 6;
        const int p = it & 63;
        const int g = h >> 1;
        float a[16];
#pragma unroll
        for (int s = 0; s < 16; ++s) a[s] = 0.0f;
#pragma unroll 4
        for (int c = 0; c < 32; ++c) {
            float qv = sm[O_QS + (h * 32 + c) * RSQ + p];
            const float4* kr = (const float4*)&sm[O_KS + (h * 32 + c) * RSS];
            float4 k0 = kr[0], k1 = kr[1], k2 = kr[2], k3 = kr[3];
            a[0] += qv * k0.x; a[1] += qv * k0.y; a[2] += qv * k0.z; a[3] += qv * k0.w;
            a[4] += qv * k1.x; a[5] += qv * k1.y; a[6] += qv * k1.z; a[7] += qv * k1.w;
            a[8] += qv * k2.x; a[9] += qv * k2.y; a[10] += qv * k2.z; a[11] += qv * k2.w;
            a[12] += qv * k3.x; a[13] += qv * k3.y; a[14] += qv * k3.z; a[15] += qv * k3.w;
        }
        const float scale = 0.17677669529663687f;
        float qy = (2 * (p >> 3) - 7) * 0.125f;
        float qx = (2 * (p & 7) - 7) * 0.125f;
        const float* rpeh = &sm[O_RPE + h * 225];
        float mx = -1e30f;
#pragma unroll
        for (int s = 0; s < 16; ++s) {
            float py = sm[O_POS + (g * 16 + s) * 2 + 0];
            float px = sm[O_POS + (g * 16 + s) * 2 + 1];
            float dy = (qy - py) * 0.5f;
            float dx = (qx - px) * 0.5f;
            float gx = (dx + 1.0f) * 7.0f;
            float gy = (dy + 1.0f) * 7.0f;
            float x0f = floorf(gx), y0f = floorf(gy);
            int jx0 = (int)x0f, jy0 = (int)y0f;
            float wx1 = gx - x0f, wy1 = gy - y0f;
            float bias = 0.0f;
            if (jx0 >= 0 && jx0 <= 14 && jy0 >= 0 && jy0 <= 14)
                bias += (1.0f - wx1) * (1.0f - wy1) * rpeh[jy0 * 15 + jx0];
            if (jx0 + 1 >= 0 && jx0 + 1 <= 14 && jy0 >= 0 && jy0 <= 14)
                bias += wx1 * (1.0f - wy1) * rpeh[jy0 * 15 + jx0 + 1];
            if (jx0 >= 0 && jx0 <= 14 && jy0 + 1 >= 0 && jy0 + 1 <= 14)
                bias += (1.0f - wx1) * wy1 * rpeh[(jy0 + 1) * 15 + jx0];
            if (jx0 + 1 >= 0 && jx0 + 1 <= 14 && jy0 + 1 >= 0 && jy0 + 1 <= 14)
                bias += wx1 * wy1 * rpeh[(jy0 + 1) * 15 + jx0 + 1];
            a[s] = a[s] * scale + bias;
            mx = fmaxf(mx, a[s]);
        }
        float ssum = 0.0f;
#pragma unroll
        for (int s = 0; s < 16; ++s) { a[s] = __expf(a[s] - mx); ssum += a[s]; }
        float inv = 1.0f / ssum;
#pragma unroll
        for (int s = 0; s < 16; ++s) a[s] *= inv;
#pragma unroll 4
        for (int cl = 0; cl < 32; ++cl) {
            int c = h * 32 + cl;
            const float4* vr = (const float4*)&sm[O_VS + c * RSS];
            float4 v0 = vr[0], v1 = vr[1], v2 = vr[2], v3 = vr[3];
            float acc = a[0]*v0.x + a[1]*v0.y + a[2]*v0.z + a[3]*v0.w
                      + a[4]*v1.x + a[5]*v1.y + a[6]*v1.z + a[7]*v1.w
                      + a[8]*v2.x + a[9]*v2.y + a[10]*v2.z + a[11]*v2.w
                      + a[12]*v3.x + a[13]*v3.y + a[14]*v3.z + a[15]*v3.w;
            sm[O_XS + c * RSX + p] = acc;
        }
    }
    __syncthreads();

    // ---- y = Wo out + bo (direct to gmem) ----
    gemm_big<false>(wo, bo, O_XS, out + (size_t)b * (CDIM * NPOS), sm, tid, wreg);
}

extern "C" void kernel_launch(void* const* d_in, const int* in_sizes, int n_in,
                              void* d_out, int out_size)
{
    (void)in_sizes; (void)n_in;
    const float* x   = (const float*)d_in[0];
    const float* wq  = (const float*)d_in[1];
    const float* bq  = (const float*)d_in[2];
    const float* wk  = (const float*)d_in[3];
    const float* bk  = (const float*)d_in[4];
    const float* wv  = (const float*)d_in[5];
    const float* bv  = (const float*)d_in[6];
    const float* wo  = (const float*)d_in[7];
    const float* bo  = (const float*)d_in[8];
    const float* dww = (const float*)d_in[9];
    const float* dwb = (const float*)d_in[10];
    const float* lng = (const float*)d_in[11];
    const float* lnb = (const float*)d_in[12];
    const float* pww = (const float*)d_in[13];
    const float* rpe = (const float*)d_in[14];
    float* out = (float*)d_out;

    int writePR = (out_size >= (REF_OFF + PR_SIZE)) ? 1 : 0;

    cudaFuncSetAttribute(dat_fused_kernel,
                         cudaFuncAttributeMaxDynamicSharedMemorySize, SMEM_BYTES);
    dat_fused_kernel<<<NBATCH, TPB, SMEM_BYTES>>>(
        x, wq, bq, wk, bk, wv, bv, wo, bo, dww, dwb, lng, lnb, pww, rpe, out, writePR);
}

// round 6
// speedup vs baseline: 1.3796x; 1.1010x over previous
#include <cuda_runtime.h>
#include <cstdint>

#define TPB 512

#define NBATCH 2048
#define CDIM 192
#define NPOS 64
#define NHEAD 6
#define NGRP 3
#define NS 16

#define RSX 68     // row stride for x / attn-out tile [192][64]
#define RSQ 68     // row stride for q tile [192][64]
#define RT64 64    // row stride, transposed 64-row weight chunk [192 k][64 co]
#define RT128 128  // row stride, transposed 128-row weight chunk [192 k][128 co]
#define RSS 16     // row stride for samp/k/v tiles [192][16]

// shared-memory layout (float offsets)
#define O_XS    0          // 13056 (x; later attn-out)
#define O_QS    13056      // 13056
#define O_WT    26112      // UNION: weight chunk (max 192*128 = 24576)  OR  samp/k/v
#define O_SAMP  (O_WT)             // 3072
#define O_KS    (O_WT + 3072)      // 3072
#define O_VS    (O_WT + 6144)      // 3072
// persistent tail (never aliased by WT)
#define O_RPE   50688      // 1350
#define O_DWW   52038      // 576
#define O_DWB   52614      // 64
#define O_LNG   52678      // 64
#define O_LNB   52742      // 64
#define O_PWW   52806      // 128
#define O_POS   52934      // 96
#define O_SMPW  53030      // 192
#define O_SMPI  53222      // 192 (ints)
#define SMEMF   53414
#define SMEM_BYTES (SMEMF * 4)   // 213656 B

#define Y_SIZE   (NBATCH * CDIM * NPOS)
#define PR_SIZE  (NBATCH * NGRP * NS * 2)
#define POS_OFF  Y_SIZE
#define REF_OFF  (Y_SIZE + PR_SIZE)

// ---- 64-row weight chunk staging (transposed): thread owns row i=tid&63, quads tid>>6 + j*8 ----
__device__ __forceinline__ void ldg_chunk64(const float* __restrict__ W, int co0,
                                            int tid, float4 r[6])
{
    const int i = tid & 63;
    const int cq = tid >> 6;    // 0..7
#pragma unroll
    for (int j = 0; j < 6; ++j)
        r[j] = __ldg((const float4*)&W[(co0 + i) * 192 + (cq + j * 8) * 4]);
}

__device__ __forceinline__ void sts_chunk64(float* __restrict__ sm, int tid, const float4 r[6])
{
    const int i = tid & 63;
    const int cq = tid >> 6;
#pragma unroll
    for (int j = 0; j < 6; ++j) {
        const int c = (cq + j * 8) * 4;
        sm[O_WT + (c + 0) * RT64 + i] = r[j].x;
        sm[O_WT + (c + 1) * RT64 + i] = r[j].y;
        sm[O_WT + (c + 2) * RT64 + i] = r[j].z;
        sm[O_WT + (c + 3) * RT64 + i] = r[j].w;
    }
}

// ---- 128-row weight chunk staging (transposed): thread owns row i=tid&127, quads tid>>7 + j*4 ----
__device__ __forceinline__ void ldg_chunk128(const float* __restrict__ W, int co0,
                                             int tid, float4 r[12])
{
    const int i = tid & 127;
    const int cq = tid >> 7;    // 0..3
#pragma unroll
    for (int j = 0; j < 12; ++j)
        r[j] = __ldg((const float4*)&W[(co0 + i) * 192 + (cq + j * 4) * 4]);
}

__device__ __forceinline__ void sts_chunk128(float* __restrict__ sm, int tid, const float4 r[12])
{
    const int i = tid & 127;
    const int cq = tid >> 7;
#pragma unroll
    for (int j = 0; j < 12; ++j) {
        const int c = (cq + j * 4) * 4;
        sm[O_WT + (c + 0) * RT128 + i] = r[j].x;
        sm[O_WT + (c + 1) * RT128 + i] = r[j].y;
        sm[O_WT + (c + 2) * RT128 + i] = r[j].z;
        sm[O_WT + (c + 3) * RT128 + i] = r[j].w;
    }
}

// 192x64 GEMM, K=192: out[co][p] = bias[co] + sum_k W[co][k] * in[k][p]
// chunk0 = rows 0..63 (2co x 4p), chunk1 = rows 64..191 (4co x 4p).
// wreg holds chunk0 on entry (prefetched by caller).
template <bool TO_SMEM>
__device__ __forceinline__ void gemm_big(const float* __restrict__ W, const float* __restrict__ bias,
                                         int inOff, float* __restrict__ gout,
                                         float* __restrict__ sm, int tid, float4 wreg[6])
{
    const int p = (tid & 15) * 4;

    // ---- chunk0: 64 rows ----
    sts_chunk64(sm, tid, wreg);
    __syncthreads();
    float4 wbig[12];
    ldg_chunk128(W, 64, tid, wbig);   // overlap with chunk0 compute
    {
        const int col = (tid >> 4) * 2;   // 0..62
        const float b0 = bias[col];
        const float b1 = bias[col + 1];
        float4 a0 = make_float4(b0, b0, b0, b0);
        float4 a1 = make_float4(b1, b1, b1, b1);
#pragma unroll 4
        for (int k = 0; k < 192; ++k) {
            float2 w = *(const float2*)&sm[O_WT + k * RT64 + col];
            float4 xv = *(const float4*)&sm[inOff + k * RSX + p];
            a0.x += w.x * xv.x; a0.y += w.x * xv.y; a0.z += w.x * xv.z; a0.w += w.x * xv.w;
            a1.x += w.y * xv.x; a1.y += w.y * xv.y; a1.z += w.y * xv.z; a1.w += w.y * xv.w;
        }
        if (TO_SMEM) {
            *(float4*)&sm[O_QS + (col) * RSQ + p] = a0;
            *(float4*)&sm[O_QS + (col + 1) * RSQ + p] = a1;
        } else {
            *(float4*)&gout[(col) * 64 + p] = a0;
            *(float4*)&gout[(col + 1) * 64 + p] = a1;
        }
    }
    __syncthreads();                  // all readers done with 64-row WT

    // ---- chunk1: 128 rows ----
    sts_chunk128(sm, tid, wbig);
    __syncthreads();
    {
        const int col = (tid >> 4) * 4;   // 0..124
        float4 a0, a1, a2, a3;
        {
            float b0 = bias[64 + col], b1 = bias[64 + col + 1];
            float b2 = bias[64 + col + 2], b3 = bias[64 + col + 3];
            a0 = make_float4(b0, b0, b0, b0);
            a1 = make_float4(b1, b1, b1, b1);
            a2 = make_float4(b2, b2, b2, b2);
            a3 = make_float4(b3, b3, b3, b3);
        }
#pragma unroll 4
        for (int k = 0; k < 192; ++k) {
            float4 w = *(const float4*)&sm[O_WT + k * RT128 + col];
            float4 xv = *(const float4*)&sm[inOff + k * RSX + p];
            a0.x += w.x * xv.x; a0.y += w.x * xv.y; a0.z += w.x * xv.z; a0.w += w.x * xv.w;
            a1.x += w.y * xv.x; a1.y += w.y * xv.y; a1.z += w.y * xv.z; a1.w += w.y * xv.w;
            a2.x += w.z * xv.x; a2.y += w.z * xv.y; a2.z += w.z * xv.z; a2.w += w.z * xv.w;
            a3.x += w.w * xv.x; a3.y += w.w * xv.y; a3.z += w.w * xv.z; a3.w += w.w * xv.w;
        }
        if (TO_SMEM) {
            *(float4*)&sm[O_QS + (64 + col) * RSQ + p] = a0;
            *(float4*)&sm[O_QS + (64 + col + 1) * RSQ + p] = a1;
            *(float4*)&sm[O_QS + (64 + col + 2) * RSQ + p] = a2;
            *(float4*)&sm[O_QS + (64 + col + 3) * RSQ + p] = a3;
        } else {
            *(float4*)&gout[(64 + col) * 64 + p] = a0;
            *(float4*)&gout[(64 + col + 1) * 64 + p] = a1;
            *(float4*)&gout[(64 + col + 2) * 64 + p] = a2;
            *(float4*)&gout[(64 + col + 3) * 64 + p] = a3;
        }
    }
    __syncthreads();
}

__global__ void __launch_bounds__(TPB, 1)
dat_fused_kernel(const float* __restrict__ x,
                 const float* __restrict__ wq, const float* __restrict__ bq,
                 const float* __restrict__ wk, const float* __restrict__ bk,
                 const float* __restrict__ wv, const float* __restrict__ bv,
                 const float* __restrict__ wo, const float* __restrict__ bo,
                 const float* __restrict__ dww, const float* __restrict__ dwb,
                 const float* __restrict__ lng, const float* __restrict__ lnb,
                 const float* __restrict__ pww, const float* __restrict__ rpe,
                 float* __restrict__ out, int writePR)
{
    extern __shared__ float sm[];
    const int b = blockIdx.x;
    const int tid = threadIdx.x;

    // prefetch q-proj weight chunk0 while staging x
    float4 wreg[6];
    ldg_chunk64(wq, 0, tid, wreg);

    // ---- stage x (transpose to [c][p]) and persistent params ----
    const float* xb = x + (size_t)b * (NPOS * CDIM);
    for (int t = tid; t < NPOS * CDIM; t += TPB) {
        int p = t / CDIM;
        int c = t - p * CDIM;
        sm[O_XS + c * RSX + p] = xb[t];
    }
    for (int t = tid; t < 1350; t += TPB) sm[O_RPE + t] = rpe[t];
    for (int t = tid; t < 576; t += TPB) sm[O_DWW + t] = dww[t];
    if (tid < 64) {
        sm[O_DWB + tid] = dwb[tid];
        sm[O_LNG + tid] = lng[tid];
        sm[O_LNB + tid] = lnb[tid];
    }
    if (tid >= 64 && tid < 192) sm[O_PWW + tid - 64] = pww[tid - 64];
    __syncthreads();

    // ---- q = Wq x + bq ----
    gemm_big<true>(wq, bq, O_XS, nullptr, sm, tid, wreg);

    // ---- offset network: 48 items (group g, sample s), 3 per warp ----
    const int warp = tid >> 5, lane = tid & 31;
    for (int kk = 0; kk < 3; ++kk) {
        const int item = warp * 3 + kk;
        const int g = item >> 4;
        const int s = item & 15;
        const int si = s >> 2, sj = s & 3;
        const int ch0 = lane, ch1 = lane + 32;
        float v0 = sm[O_DWB + ch0];
        float v1 = sm[O_DWB + ch1];
        const int iy0 = 2 * si - 1, ix0 = 2 * sj - 1;
#pragma unroll
        for (int di = 0; di < 3; ++di) {
            int iy = iy0 + di;
            if (iy < 0 || iy > 7) continue;
#pragma unroll
            for (int dj = 0; dj < 3; ++dj) {
                int ix = ix0 + dj;
                if (ix < 0 || ix > 7) continue;
                float q0 = sm[O_QS + (g * 64 + ch0) * RSQ + iy * 8 + ix];
                float q1 = sm[O_QS + (g * 64 + ch1) * RSQ + iy * 8 + ix];
                v0 += sm[O_DWW + ch0 * 9 + di * 3 + dj] * q0;
                v1 += sm[O_DWW + ch1 * 9 + di * 3 + dj] * q1;
            }
        }
        float ssum = v0 + v1, ssq = v0 * v0 + v1 * v1;
#pragma unroll
        for (int o = 16; o > 0; o >>= 1) {
            ssum += __shfl_xor_sync(0xffffffffu, ssum, o);
            ssq += __shfl_xor_sync(0xffffffffu, ssq, o);
        }
        float mu = ssum * (1.0f / 64.0f);
        float var = ssq * (1.0f / 64.0f) - mu * mu;
        float rstd = rsqrtf(var + 1e-5f);
        v0 = (v0 - mu) * rstd * sm[O_LNG + ch0] + sm[O_LNB + ch0];
        v1 = (v1 - mu) * rstd * sm[O_LNG + ch1] + sm[O_LNB + ch1];
        v0 = 0.5f * v0 * (1.0f + erff(v0 * 0.70710678118654752f));
        v1 = 0.5f * v1 * (1.0f + erff(v1 * 0.70710678118654752f));
        float o0 = sm[O_PWW + ch0] * v0 + sm[O_PWW + ch1] * v1;
        float o1 = sm[O_PWW + 64 + ch0] * v0 + sm[O_PWW + 64 + ch1] * v1;
#pragma unroll
        for (int o = 16; o > 0; o >>= 1) {
            o0 += __shfl_xor_sync(0xffffffffu, o0, o);
            o1 += __shfl_xor_sync(0xffffffffu, o1, o);
        }
        if (lane == 0) {
            float offy = tanhf(o0) * (2.0f / 3.0f);
            float offx = tanhf(o1) * (2.0f / 3.0f);
            float ry = (2 * si - 3) * 0.25f;
            float rx = (2 * sj - 3) * 0.25f;
            float py = offy + ry;
            float px = offx + rx;
            sm[O_POS + item * 2 + 0] = py;
            sm[O_POS + item * 2 + 1] = px;
            float gx = (px + 1.0f) * 3.5f;
            float gy = (py + 1.0f) * 3.5f;
            float x0f = floorf(gx), y0f = floorf(gy);
            int jx0 = (int)x0f, jy0 = (int)y0f;
            float wx1 = gx - x0f, wy1 = gy - y0f;
            float wxs[2] = {1.0f - wx1, wx1};
            float wys[2] = {1.0f - wy1, wy1};
            int* smpI = (int*)sm;
#pragma unroll
            for (int n = 0; n < 4; ++n) {
                int xi = jx0 + (n & 1);
                int yi = jy0 + (n >> 1);
                bool val = (xi >= 0 && xi <= 7 && yi >= 0 && yi <= 7);
                sm[O_SMPW + item * 4 + n] = val ? wxs[n & 1] * wys[n >> 1] : 0.0f;
                smpI[O_SMPI + item * 4 + n] = val ? (yi * 8 + xi) : 0;
            }
            if (writePR) {
                size_t po = ((size_t)b * 48 + item) * 2;
                out[POS_OFF + po + 0] = py;
                out[POS_OFF + po + 1] = px;
                out[REF_OFF + po + 0] = ry;
                out[REF_OFF + po + 1] = rx;
            }
        }
    }
    __syncthreads();

    // ---- bilinear sample x at pos -> samp[c][s] ----
    for (int t = tid; t < CDIM * NS; t += TPB) {
        int c = t >> 4;
        int s = t & 15;
        int item = (c >> 6) * 16 + s;
        const float* wp = &sm[O_SMPW + item * 4];
        const int* ip = ((const int*)sm) + O_SMPI + item * 4;
        const float* row = &sm[O_XS + c * RSX];
        sm[O_SAMP + c * RSS + s] =
            wp[0] * row[ip[0]] + wp[1] * row[ip[1]] + wp[2] * row[ip[2]] + wp[3] * row[ip[3]];
    }
    __syncthreads();

    // ---- k, v projections: weights direct from L2, thread = (co, 8 s-cols) ----
    if (tid < 384) {
        const int co = tid >> 1;
        const int sh = (tid & 1) * 8;
        const float bkc = bk[co], bvc = bv[co];
        float4 ak0 = make_float4(bkc, bkc, bkc, bkc), ak1 = ak0;
        float4 av0 = make_float4(bvc, bvc, bvc, bvc), av1 = av0;
#pragma unroll 4
        for (int k4 = 0; k4 < 48; ++k4) {
            float4 wk4 = __ldg((const float4*)&wk[co * 192 + k4 * 4]);
            float4 wv4 = __ldg((const float4*)&wv[co * 192 + k4 * 4]);
#pragma unroll
            for (int j = 0; j < 4; ++j) {
                float wkj = (j == 0) ? wk4.x : (j == 1) ? wk4.y : (j == 2) ? wk4.z : wk4.w;
                float wvj = (j == 0) ? wv4.x : (j == 1) ? wv4.y : (j == 2) ? wv4.z : wv4.w;
                float4 s0 = *(const float4*)&sm[O_SAMP + (k4 * 4 + j) * RSS + sh];
                float4 s1 = *(const float4*)&sm[O_SAMP + (k4 * 4 + j) * RSS + sh + 4];
                ak0.x += wkj * s0.x; ak0.y += wkj * s0.y; ak0.z += wkj * s0.z; ak0.w += wkj * s0.w;
                ak1.x += wkj * s1.x; ak1.y += wkj * s1.y; ak1.z += wkj * s1.z; ak1.w += wkj * s1.w;
                av0.x += wvj * s0.x; av0.y += wvj * s0.y; av0.z += wvj * s0.z; av0.w += wvj * s0.w;
                av1.x += wvj * s1.x; av1.y += wvj * s1.y; av1.z += wvj * s1.z; av1.w += wvj * s1.w;
            }
        }
        *(float4*)&sm[O_KS + co * RSS + sh] = ak0;
        *(float4*)&sm[O_KS + co * RSS + sh + 4] = ak1;
        *(float4*)&sm[O_VS + co * RSS + sh] = av0;
        *(float4*)&sm[O_VS + co * RSS + sh + 4] = av1;
    }
    __syncthreads();

    // prefetch o-proj weight chunk0; attention below hides the L2 latency
    ldg_chunk64(wo, 0, tid, wreg);

    // ---- attention: item = (head, query position), 384 items ----
    for (int it = tid; it < NHEAD * NPOS; it += TPB) {
        const int h = it >> 6;
        const int p = it & 63;
        const int g = h >> 1;
        float a[16];
#pragma unroll
        for (int s = 0; s < 16; ++s) a[s] = 0.0f;
#pragma unroll 4
        for (int c = 0; c < 32; ++c) {
            float qv = sm[O_QS + (h * 32 + c) * RSQ + p];
            const float4* kr = (const float4*)&sm[O_KS + (h * 32 + c) * RSS];
            float4 k0 = kr[0], k1 = kr[1], k2 = kr[2], k3 = kr[3];
            a[0] += qv * k0.x; a[1] += qv * k0.y; a[2] += qv * k0.z; a[3] += qv * k0.w;
            a[4] += qv * k1.x; a[5] += qv * k1.y; a[6] += qv * k1.z; a[7] += qv * k1.w;
            a[8] += qv * k2.x; a[9] += qv * k2.y; a[10] += qv * k2.z; a[11] += qv * k2.w;
            a[12] += qv * k3.x; a[13] += qv * k3.y; a[14] += qv * k3.z; a[15] += qv * k3.w;
        }
        const float scale = 0.17677669529663687f;
        float qy = (2 * (p >> 3) - 7) * 0.125f;
        float qx = (2 * (p & 7) - 7) * 0.125f;
        const float* rpeh = &sm[O_RPE + h * 225];
        float mx = -1e30f;
#pragma unroll
        for (int s = 0; s < 16; ++s) {
            float py = sm[O_POS + (g * 16 + s) * 2 + 0];
            float px = sm[O_POS + (g * 16 + s) * 2 + 1];
            float dy = (qy - py) * 0.5f;
            float dx = (qx - px) * 0.5f;
            float gx = (dx + 1.0f) * 7.0f;
            float gy = (dy + 1.0f) * 7.0f;
            float x0f = floorf(gx), y0f = floorf(gy);
            int jx0 = (int)x0f, jy0 = (int)y0f;
            float wx1 = gx - x0f, wy1 = gy - y0f;
            float bias = 0.0f;
            if (jx0 >= 0 && jx0 <= 14 && jy0 >= 0 && jy0 <= 14)
                bias += (1.0f - wx1) * (1.0f - wy1) * rpeh[jy0 * 15 + jx0];
            if (jx0 + 1 >= 0 && jx0 + 1 <= 14 && jy0 >= 0 && jy0 <= 14)
                bias += wx1 * (1.0f - wy1) * rpeh[jy0 * 15 + jx0 + 1];
            if (jx0 >= 0 && jx0 <= 14 && jy0 + 1 >= 0 && jy0 + 1 <= 14)
                bias += (1.0f - wx1) * wy1 * rpeh[(jy0 + 1) * 15 + jx0];
            if (jx0 + 1 >= 0 && jx0 + 1 <= 14 && jy0 + 1 >= 0 && jy0 + 1 <= 14)
                bias += wx1 * wy1 * rpeh[(jy0 + 1) * 15 + jx0 + 1];
            a[s] = a[s] * scale + bias;
            mx = fmaxf(mx, a[s]);
        }
        float ssum = 0.0f;
#pragma unroll
        for (int s = 0; s < 16; ++s) { a[s] = __expf(a[s] - mx); ssum += a[s]; }
        float inv = 1.0f / ssum;
#pragma unroll
        for (int s = 0; s < 16; ++s) a[s] *= inv;
#pragma unroll 4
        for (int cl = 0; cl < 32; ++cl) {
            int c = h * 32 + cl;
            const float4* vr = (const float4*)&sm[O_VS + c * RSS];
            float4 v0 = vr[0], v1 = vr[1], v2 = vr[2], v3 = vr[3];
            float acc = a[0]*v0.x + a[1]*v0.y + a[2]*v0.z + a[3]*v0.w
                      + a[4]*v1.x + a[5]*v1.y + a[6]*v1.z + a[7]*v1.w
                      + a[8]*v2.x + a[9]*v2.y + a[10]*v2.z + a[11]*v2.w
                      + a[12]*v3.x + a[13]*v3.y + a[14]*v3.z + a[15]*v3.w;
            sm[O_XS + c * RSX + p] = acc;
        }
    }
    __syncthreads();

    // ---- y = Wo out + bo (direct to gmem) ----
    gemm_big<false>(wo, bo, O_XS, out + (size_t)b * (CDIM * NPOS), sm, tid, wreg);
}

extern "C" void kernel_launch(void* const* d_in, const int* in_sizes, int n_in,
                              void* d_out, int out_size)
{
    (void)in_sizes; (void)n_in;
    const float* x   = (const float*)d_in[0];
    const float* wq  = (const float*)d_in[1];
    const float* bq  = (const float*)d_in[2];
    const float* wk  = (const float*)d_in[3];
    const float* bk  = (const float*)d_in[4];
    const float* wv  = (const float*)d_in[5];
    const float* bv  = (const float*)d_in[6];
    const float* wo  = (const float*)d_in[7];
    const float* bo  = (const float*)d_in[8];
    const float* dww = (const float*)d_in[9];
    const float* dwb = (const float*)d_in[10];
    const float* lng = (const float*)d_in[11];
    const float* lnb = (const float*)d_in[12];
    const float* pww = (const float*)d_in[13];
    const float* rpe = (const float*)d_in[14];
    float* out = (float*)d_out;

    int writePR = (out_size >= (REF_OFF + PR_SIZE)) ? 1 : 0;

    cudaFuncSetAttribute(dat_fused_kernel,
                         cudaFuncAttributeMaxDynamicSharedMemorySize, SMEM_BYTES);
    dat_fused_kernel<<<NBATCH, TPB, SMEM_BYTES>>>(
        x, wq, bq, wk, bk, wv, bv, wo, bo, dww, dwb, lng, lnb, pww, rpe, out, writePR);
}